// round 8
// baseline (speedup 1.0000x reference)
#include <cuda_runtime.h>
#include <cstdint>

// ---------------- problem constants ----------------
#define T_TOK 2048
#define HDIM  1024
#define IDIM  1024
#define NEXP  8
#define NSLOT (2 * T_TOK)

// ---------------- scratch (device globals) ----------------
__device__ int   g_offsets[NEXP + 1];
__device__ float g_tok_w[T_TOK * 2];
__device__ int   g_tok_slot[T_TOK * 2];
__device__ int   g_row_token[NSLOT];
__device__ float g_inter[(size_t)NSLOT * IDIM];     // fp32 intermediate
__device__ float g_out_slot[(size_t)NSLOT * HDIM];  // per-slot expert output

// ---------------- helpers ----------------
__device__ __forceinline__ uint32_t f2tf(float f) {
    uint32_t r; asm("cvt.rna.tf32.f32 %0, %1;" : "=r"(r) : "f"(f)); return r;
}
__device__ __forceinline__ uint32_t smem_u32(const void* p) {
    uint32_t a;
    asm("{ .reg .u64 t; cvta.to.shared.u64 t, %1; cvt.u32.u64 %0, t; }" : "=r"(a) : "l"(p));
    return a;
}
__device__ __forceinline__ void mma_tf32(float* d, const uint32_t* a, uint32_t b0, uint32_t b1) {
    asm volatile(
        "mma.sync.aligned.m16n8k8.row.col.f32.tf32.tf32.f32 "
        "{%0,%1,%2,%3}, {%4,%5,%6,%7}, {%8,%9}, {%0,%1,%2,%3};\n"
        : "+f"(d[0]), "+f"(d[1]), "+f"(d[2]), "+f"(d[3])
        : "r"(a[0]), "r"(a[1]), "r"(a[2]), "r"(a[3]), "r"(b0), "r"(b1));
}
__device__ __forceinline__ void ldsm_x4(uint32_t& r0, uint32_t& r1, uint32_t& r2, uint32_t& r3,
                                        uint32_t addr) {
    asm volatile("ldmatrix.sync.aligned.m8n8.x4.shared.b16 {%0,%1,%2,%3}, [%4];"
                 : "=r"(r0), "=r"(r1), "=r"(r2), "=r"(r3) : "r"(addr));
}
#define CP_ASYNC16(dst, src) \
    asm volatile("cp.async.cg.shared.global [%0], [%1], 16;" :: "r"(dst), "l"(src))
#define CP_ASYNC16Z(dst, src, sz) \
    asm volatile("cp.async.cg.shared.global [%0], [%1], 16, %2;" :: "r"(dst), "l"(src), "r"(sz))
#define CP_COMMIT()  asm volatile("cp.async.commit_group;" ::: "memory")
#define CP_WAIT1()   asm volatile("cp.async.wait_group 1;" ::: "memory")
#define CP_WAIT0()   asm volatile("cp.async.wait_group 0;" ::: "memory")

// ---------------- fused router (ballot-aggregated atomics) ----------------
__global__ __launch_bounds__(1024) void route_kernel(const float* __restrict__ logits) {
    __shared__ int s_cnt[NEXP];
    __shared__ int s_cur[NEXP];
    int tid = threadIdx.x;
    int lane = tid & 31;
    if (tid < NEXP) s_cnt[tid] = 0;
    __syncthreads();

    int te[2][2];
#pragma unroll
    for (int h = 0; h < 2; h++) {
        int t = tid + h * 1024;
        float l[NEXP];
#pragma unroll
        for (int e = 0; e < NEXP; e++) l[e] = logits[t * NEXP + e];
        int i1 = 0;
#pragma unroll
        for (int e = 1; e < NEXP; e++) if (l[e] > l[i1]) i1 = e;
        int i2 = -1; float b2 = -3.0e38f;
#pragma unroll
        for (int e = 0; e < NEXP; e++) if (e != i1 && l[e] > b2) { b2 = l[e]; i2 = e; }
        float e2 = expf(l[i2] - l[i1]);
        float s = 1.0f + e2;
        te[h][0] = i1; te[h][1] = i2;
        g_tok_w[2 * t]     = 1.0f / s;
        g_tok_w[2 * t + 1] = e2 / s;
        // warp-aggregated counting
#pragma unroll
        for (int e = 0; e < NEXP; e++) {
            unsigned m1 = __ballot_sync(0xFFFFFFFFu, i1 == e);
            unsigned m2 = __ballot_sync(0xFFFFFFFFu, i2 == e);
            int cnt = __popc(m1) + __popc(m2);
            if (lane == 0 && cnt) atomicAdd(&s_cnt[e], cnt);
        }
    }
    __syncthreads();
    if (tid == 0) {
        int o = 0;
        for (int e = 0; e < NEXP; e++) { g_offsets[e] = o; s_cur[e] = o; o += s_cnt[e]; }
        g_offsets[NEXP] = o;
    }
    __syncthreads();
    unsigned ltmask = (1u << lane) - 1u;
#pragma unroll
    for (int h = 0; h < 2; h++) {
        int t = tid + h * 1024;
#pragma unroll
        for (int e = 0; e < NEXP; e++) {
            unsigned m1 = __ballot_sync(0xFFFFFFFFu, te[h][0] == e);
            unsigned m2 = __ballot_sync(0xFFFFFFFFu, te[h][1] == e);
            int cnt = __popc(m1) + __popc(m2);
            int base = 0;
            if (lane == 0 && cnt) base = atomicAdd(&s_cur[e], cnt);
            base = __shfl_sync(0xFFFFFFFFu, base, 0);
            if (te[h][0] == e) {
                int slot = base + __popc(m1 & ltmask);
                g_row_token[slot] = t;
                g_tok_slot[2 * t] = slot;
            }
            if (te[h][1] == e) {
                int slot = base + __popc(m1) + __popc(m2 & ltmask);
                g_row_token[slot] = t;
                g_tok_slot[2 * t + 1] = slot;
            }
        }
    }
}

// ---------------- GEMM tiling ----------------
// BM=128, BK=32, 256 threads (8 warps in 4Mx2N layout, 32x32 warp tile per matrix)
// A row stride 36 words -> ldmatrix rows conflict-free; B row stride BN+8 -> frag LDS conflict-free
#define BM   128
#define BK   32
#define AST  36
#define NSTG 3

// ================= GEMM1: x @ w13 -> SwiGLU -> g_inter =================
#define G1_BN   64
#define G1_BST  72
#define G1_AW   (BM * AST)                 // 4608 words
#define G1_BW   (BK * G1_BST)              // 2304 words
#define G1_STW  (G1_AW + 2 * G1_BW)        // 9216 words per stage
#define G1_SMEM (NSTG * G1_STW * 4)        // 110592 bytes

__global__ __launch_bounds__(256, 2) void gemm1_kernel(const float* __restrict__ x,
                                                       const float* __restrict__ w13) {
    extern __shared__ float sm[];
    __shared__ int s_tok[BM];

    const int e = blockIdx.z;
    const int seg = g_offsets[e];
    const int rows = g_offsets[e + 1] - seg;
    const int m0 = blockIdx.y * BM;
    if (m0 >= rows) return;
    const int n0 = blockIdx.x * G1_BN;
    const int tid = threadIdx.x;
    const int warp = tid >> 5, lane = tid & 31;
    const int wm = (warp >> 1) * 32, wn = (warp & 1) * 32;
    const int qid = lane >> 2, tq = lane & 3;
    // ldmatrix per-thread source row/colgroup
    const int lmrow = (lane & 7) + ((lane >> 3) & 1) * 8;
    const int lmc4  = (lane >> 4) * 4;

    if (tid < BM) {
        int gr = m0 + tid;
        s_tok[tid] = (gr < rows) ? g_row_token[seg + gr] : -1;
    }
    __syncthreads();

    const float* wg = w13 + (size_t)e * HDIM * (2 * IDIM);

    const int a_row = tid >> 1;
    const int a_f4  = (tid & 1) * 4;
    const int b_row = tid >> 4;
    const int b_f4  = tid & 15;
    const int tok_a = s_tok[a_row];
    const float* a_src0 = (tok_a >= 0) ? (x + (size_t)tok_a * HDIM) : x;
    const uint32_t a_sz = (tok_a >= 0) ? 16u : 0u;

    auto load_chunk = [&](int c, int s) {
        float* As = sm + s * G1_STW;
        float* Bg = As + G1_AW;
        float* Bu = Bg + G1_BW;
        const int k0 = c * BK;
#pragma unroll
        for (int j = 0; j < 4; j++) {
            int f4 = a_f4 + j;
            CP_ASYNC16Z(smem_u32(&As[a_row * AST + f4 * 4]), a_src0 + k0 + f4 * 4, a_sz);
        }
#pragma unroll
        for (int p = 0; p < 2; p++) {
            int kr = b_row + p * 16;
            const float* srow = wg + (size_t)(k0 + kr) * (2 * IDIM);
            CP_ASYNC16(smem_u32(&Bg[kr * G1_BST + b_f4 * 4]), srow + n0 + b_f4 * 4);
            CP_ASYNC16(smem_u32(&Bu[kr * G1_BST + b_f4 * 4]), srow + IDIM + n0 + b_f4 * 4);
        }
    };

    float accg[2][4][4] = {};
    float accu[2][4][4] = {};

    load_chunk(0, 0); CP_COMMIT();
    load_chunk(1, 1); CP_COMMIT();

    const int NC = HDIM / BK;   // 32
    for (int c = 0; c < NC; c++) {
        if (c + 2 < NC) CP_WAIT1(); else CP_WAIT0();
        __syncthreads();
        if (c + 2 < NC) { load_chunk(c + 2, (c + 2) % NSTG); CP_COMMIT(); }

        const int sc = c % NSTG;
        const float* As = sm + sc * G1_STW;
        const float* Bg = As + G1_AW;
        const float* Bu = Bg + G1_BW;

        const uint32_t alm0 = smem_u32(&As[(wm + lmrow) * AST + lmc4]);
        const uint32_t alm1 = smem_u32(&As[(wm + 16 + lmrow) * AST + lmc4]);

#pragma unroll
        for (int ks = 0; ks < BK; ks += 8) {
            uint32_t af[2][4];
            {
                uint32_t r0, r1, r2, r3;
                ldsm_x4(r0, r1, r2, r3, alm0 + ks * 4);
                af[0][0] = f2tf(__uint_as_float(r0));
                af[0][1] = f2tf(__uint_as_float(r1));
                af[0][2] = f2tf(__uint_as_float(r2));
                af[0][3] = f2tf(__uint_as_float(r3));
                ldsm_x4(r0, r1, r2, r3, alm1 + ks * 4);
                af[1][0] = f2tf(__uint_as_float(r0));
                af[1][1] = f2tf(__uint_as_float(r1));
                af[1][2] = f2tf(__uint_as_float(r2));
                af[1][3] = f2tf(__uint_as_float(r3));
            }
#pragma unroll
            for (int nt = 0; nt < 4; nt++) {
                int cc = wn + nt * 8 + qid;
                uint32_t bg0 = f2tf(Bg[(ks + tq) * G1_BST + cc]);
                uint32_t bg1 = f2tf(Bg[(ks + tq + 4) * G1_BST + cc]);
                uint32_t bu0 = f2tf(Bu[(ks + tq) * G1_BST + cc]);
                uint32_t bu1 = f2tf(Bu[(ks + tq + 4) * G1_BST + cc]);
#pragma unroll
                for (int mt = 0; mt < 2; mt++) {
                    mma_tf32(accg[mt][nt], af[mt], bg0, bg1);
                    mma_tf32(accu[mt][nt], af[mt], bu0, bu1);
                }
            }
        }
    }

    // epilogue: SwiGLU -> g_inter (fp32)
#pragma unroll
    for (int mt = 0; mt < 2; mt++) {
#pragma unroll
        for (int nt = 0; nt < 4; nt++) {
            int rbase = wm + mt * 16 + qid;
            int cbase = n0 + wn + nt * 8 + tq * 2;
#pragma unroll
            for (int i = 0; i < 4; i++) {
                int r = rbase + ((i >> 1) * 8);
                int cc = cbase + (i & 1);
                int gr = m0 + r;
                if (gr < rows) {
                    float g = accg[mt][nt][i];
                    float u = accu[mt][nt][i];
                    float sig = 1.0f / (1.0f + expf(-g));
                    g_inter[(size_t)(seg + gr) * IDIM + cc] = g * sig * u;
                }
            }
        }
    }
}

// ================= GEMM2: g_inter @ w2 -> g_out_slot =================
#define G2_BN   128
#define G2_BST  136
#define G2_AW   (BM * AST)                 // 4608 words
#define G2_BW   (BK * G2_BST)              // 4352 words
#define G2_STW  (G2_AW + G2_BW)            // 8960 words
#define G2_SMEM (NSTG * G2_STW * 4)        // 107520 bytes

__global__ __launch_bounds__(256, 2) void gemm2_kernel(const float* __restrict__ w2) {
    extern __shared__ float sm[];

    const int e = blockIdx.z;
    const int seg = g_offsets[e];
    const int rows = g_offsets[e + 1] - seg;
    const int m0 = blockIdx.y * BM;
    if (m0 >= rows) return;
    const int n0 = blockIdx.x * G2_BN;
    const int tid = threadIdx.x;
    const int warp = tid >> 5, lane = tid & 31;
    const int wm = (warp >> 1) * 32, wn = (warp & 1) * 64;
    const int qid = lane >> 2, tq = lane & 3;
    const int lmrow = (lane & 7) + ((lane >> 3) & 1) * 8;
    const int lmc4  = (lane >> 4) * 4;

    const float* wb = w2 + (size_t)e * IDIM * HDIM;

    const int a_row = tid >> 1;
    const int a_f4  = (tid & 1) * 4;
    const int gra = m0 + a_row;
    const bool avalid = (gra < rows);
    const float* a_src0 = avalid ? (g_inter + (size_t)(seg + gra) * IDIM) : g_inter;
    const uint32_t a_sz = avalid ? 16u : 0u;
    const int b_row = tid >> 5;
    const int b_f4  = tid & 31;

    auto load_chunk = [&](int c, int s) {
        float* As = sm + s * G2_STW;
        float* Bs = As + G2_AW;
        const int k0 = c * BK;
#pragma unroll
        for (int j = 0; j < 4; j++) {
            int f4 = a_f4 + j;
            CP_ASYNC16Z(smem_u32(&As[a_row * AST + f4 * 4]), a_src0 + k0 + f4 * 4, a_sz);
        }
#pragma unroll
        for (int p = 0; p < 4; p++) {
            int kr = b_row + p * 8;
            CP_ASYNC16(smem_u32(&Bs[kr * G2_BST + b_f4 * 4]),
                       wb + (size_t)(k0 + kr) * HDIM + n0 + b_f4 * 4);
        }
    };

    float acc[2][8][4] = {};

    load_chunk(0, 0); CP_COMMIT();
    load_chunk(1, 1); CP_COMMIT();

    const int NC = IDIM / BK;   // 32
    for (int c = 0; c < NC; c++) {
        if (c + 2 < NC) CP_WAIT1(); else CP_WAIT0();
        __syncthreads();
        if (c + 2 < NC) { load_chunk(c + 2, (c + 2) % NSTG); CP_COMMIT(); }

        const int sc = c % NSTG;
        const float* As = sm + sc * G2_STW;
        const float* Bs = As + G2_AW;

        const uint32_t alm0 = smem_u32(&As[(wm + lmrow) * AST + lmc4]);
        const uint32_t alm1 = smem_u32(&As[(wm + 16 + lmrow) * AST + lmc4]);

#pragma unroll
        for (int ks = 0; ks < BK; ks += 8) {
            uint32_t af[2][4];
            {
                uint32_t r0, r1, r2, r3;
                ldsm_x4(r0, r1, r2, r3, alm0 + ks * 4);
                af[0][0] = f2tf(__uint_as_float(r0));
                af[0][1] = f2tf(__uint_as_float(r1));
                af[0][2] = f2tf(__uint_as_float(r2));
                af[0][3] = f2tf(__uint_as_float(r3));
                ldsm_x4(r0, r1, r2, r3, alm1 + ks * 4);
                af[1][0] = f2tf(__uint_as_float(r0));
                af[1][1] = f2tf(__uint_as_float(r1));
                af[1][2] = f2tf(__uint_as_float(r2));
                af[1][3] = f2tf(__uint_as_float(r3));
            }
#pragma unroll
            for (int nt = 0; nt < 8; nt++) {
                int cc = wn + nt * 8 + qid;
                uint32_t b0 = f2tf(Bs[(ks + tq) * G2_BST + cc]);
                uint32_t b1 = f2tf(Bs[(ks + tq + 4) * G2_BST + cc]);
#pragma unroll
                for (int mt = 0; mt < 2; mt++) {
                    mma_tf32(acc[mt][nt], af[mt], b0, b1);
                }
            }
        }
    }

#pragma unroll
    for (int mt = 0; mt < 2; mt++) {
#pragma unroll
        for (int nt = 0; nt < 8; nt++) {
            int rbase = wm + mt * 16 + qid;
            int cbase = n0 + wn + nt * 8 + tq * 2;
#pragma unroll
            for (int i = 0; i < 4; i++) {
                int r = rbase + ((i >> 1) * 8);
                int cc = cbase + (i & 1);
                int gr = m0 + r;
                if (gr < rows) {
                    g_out_slot[(size_t)(seg + gr) * HDIM + cc] = acc[mt][nt][i];
                }
            }
        }
    }
}

// ---------------- combine: out[t] = w0*slot[s0] + w1*slot[s1] ----------------
__global__ __launch_bounds__(256) void combine_kernel(float* __restrict__ out) {
    int idx = blockIdx.x * blockDim.x + threadIdx.x;
    int t = idx / (HDIM / 4);
    int c4 = (idx % (HDIM / 4)) * 4;
    if (t >= T_TOK) return;
    int s0 = g_tok_slot[2 * t];
    int s1 = g_tok_slot[2 * t + 1];
    float w0 = g_tok_w[2 * t];
    float w1 = g_tok_w[2 * t + 1];
    float4 a = *(const float4*)&g_out_slot[(size_t)s0 * HDIM + c4];
    float4 b = *(const float4*)&g_out_slot[(size_t)s1 * HDIM + c4];
    float4 r;
    r.x = w0 * a.x + w1 * b.x;
    r.y = w0 * a.y + w1 * b.y;
    r.z = w0 * a.z + w1 * b.z;
    r.w = w0 * a.w + w1 * b.w;
    *(float4*)&out[(size_t)t * HDIM + c4] = r;
}

// ---------------- launch ----------------
extern "C" void kernel_launch(void* const* d_in, const int* in_sizes, int n_in,
                              void* d_out, int out_size) {
    const float* x      = (const float*)d_in[0];
    const float* logits = (const float*)d_in[1];
    const float* w13    = (const float*)d_in[2];
    const float* w2     = (const float*)d_in[3];
    float* out = (float*)d_out;

    cudaFuncSetAttribute(gemm1_kernel, cudaFuncAttributeMaxDynamicSharedMemorySize, G1_SMEM);
    cudaFuncSetAttribute(gemm2_kernel, cudaFuncAttributeMaxDynamicSharedMemorySize, G2_SMEM);

    route_kernel<<<1, 1024>>>(logits);

    gemm1_kernel<<<dim3(IDIM / G1_BN, 16, NEXP), 256, G1_SMEM>>>(x, w13);
    gemm2_kernel<<<dim3(HDIM / G2_BN, 16, NEXP), 256, G2_SMEM>>>(w2);

    combine_kernel<<<T_TOK * HDIM / 4 / 256, 256>>>(out);
}

// round 11
// speedup vs baseline: 1.7565x; 1.7565x over previous
#include <cuda_runtime.h>
#include <cuda_fp16.h>
#include <cstdint>

// ---------------- problem constants ----------------
#define T_TOK 2048
#define HDIM  1024
#define IDIM  1024
#define NEXP  8
#define NSLOT (2 * T_TOK)

// ---------------- scratch (device globals, ~29.4 MB total) ----------------
__device__ int      g_offsets[NEXP + 1];
__device__ float    g_tok_w[T_TOK * 2];
__device__ int      g_tok_slot[T_TOK * 2];
__device__ int      g_row_token[NSLOT];
__device__ uint16_t g_xh[(size_t)T_TOK * HDIM];        // x as fp16 (4.2 MB)
__device__ uint16_t g_interh[(size_t)NSLOT * IDIM];    // fp16 intermediate (8.4 MB)
__device__ float    g_out_slot[(size_t)NSLOT * HDIM];  // per-slot output (16.8 MB)

// ---------------- helpers ----------------
__device__ __forceinline__ uint32_t smem_u32(const void* p) {
    uint32_t a;
    asm("{ .reg .u64 t; cvta.to.shared.u64 t, %1; cvt.u32.u64 %0, t; }" : "=r"(a) : "l"(p));
    return a;
}
__device__ __forceinline__ void mma_f16(float* d, const uint32_t* a, uint32_t b0, uint32_t b1) {
    asm volatile(
        "mma.sync.aligned.m16n8k16.row.col.f32.f16.f16.f32 "
        "{%0,%1,%2,%3}, {%4,%5,%6,%7}, {%8,%9}, {%0,%1,%2,%3};\n"
        : "+f"(d[0]), "+f"(d[1]), "+f"(d[2]), "+f"(d[3])
        : "r"(a[0]), "r"(a[1]), "r"(a[2]), "r"(a[3]), "r"(b0), "r"(b1));
}
__device__ __forceinline__ void ldsm_x4_trans(uint32_t* r, uint32_t addr) {
    asm volatile("ldmatrix.sync.aligned.m8n8.x4.trans.shared.b16 {%0,%1,%2,%3}, [%4];"
                 : "=r"(r[0]), "=r"(r[1]), "=r"(r[2]), "=r"(r[3]) : "r"(addr));
}
#define CP_ASYNC16Z(dst, src, sz) \
    asm volatile("cp.async.cg.shared.global [%0], [%1], 16, %2;" :: "r"(dst), "l"(src), "r"(sz))
#define CP_COMMIT()  asm volatile("cp.async.commit_group;" ::: "memory")
#define CP_WAIT0()   asm volatile("cp.async.wait_group 0;" ::: "memory")

// ---------------- fused router (proven) ----------------
__global__ __launch_bounds__(1024) void route_kernel(const float* __restrict__ logits) {
    __shared__ int s_cnt[NEXP];
    __shared__ int s_cur[NEXP];
    int tid = threadIdx.x;
    if (tid < NEXP) s_cnt[tid] = 0;
    __syncthreads();

    int te[2][2];
#pragma unroll
    for (int h = 0; h < 2; h++) {
        int t = tid + h * 1024;
        float l[NEXP];
#pragma unroll
        for (int e = 0; e < NEXP; e++) l[e] = logits[t * NEXP + e];
        int i1 = 0;
#pragma unroll
        for (int e = 1; e < NEXP; e++) if (l[e] > l[i1]) i1 = e;
        int i2 = -1; float b2 = -3.0e38f;
#pragma unroll
        for (int e = 0; e < NEXP; e++) if (e != i1 && l[e] > b2) { b2 = l[e]; i2 = e; }
        float e2 = expf(l[i2] - l[i1]);
        float s = 1.0f + e2;
        te[h][0] = i1; te[h][1] = i2;
        g_tok_w[2 * t]     = 1.0f / s;
        g_tok_w[2 * t + 1] = e2 / s;
        atomicAdd(&s_cnt[i1], 1);
        atomicAdd(&s_cnt[i2], 1);
    }
    __syncthreads();
    if (tid == 0) {
        int o = 0;
        for (int e = 0; e < NEXP; e++) { g_offsets[e] = o; s_cur[e] = o; o += s_cnt[e]; }
        g_offsets[NEXP] = o;
    }
    __syncthreads();
#pragma unroll
    for (int h = 0; h < 2; h++) {
        int t = tid + h * 1024;
#pragma unroll
        for (int k = 0; k < 2; k++) {
            int slot = atomicAdd(&s_cur[te[h][k]], 1);
            g_row_token[slot] = t;
            g_tok_slot[2 * t + k] = slot;
        }
    }
}

// ---------------- prepass: x -> fp16 ----------------
__global__ __launch_bounds__(256) void cvt_x_kernel(const float* __restrict__ x) {
    size_t i = ((size_t)blockIdx.x * blockDim.x + threadIdx.x) * 4;
    float4 v = *(const float4*)(x + i);
    __half2 lo = __floats2half2_rn(v.x, v.y);
    __half2 hi = __floats2half2_rn(v.z, v.w);
    uint2 o;
    o.x = *(uint32_t*)&lo;
    o.y = *(uint32_t*)&hi;
    *(uint2*)(g_xh + i) = o;
}

// ---------------- GEMM tiling ----------------
// BM=128, BK=32, 256 threads, 8 warps (4M x 2N), warp tile 32x32.
// A smem fp16 [m][k], row stride 40 halves -> b32 fragment loads conflict-free.
// B smem fp16 [k][n], row stride 72 halves -> ldmatrix rows at banks 4k, conflict-free.
#define BM   128
#define BK   32
#define ASTH 40
#define BSTH 72
#define A_H  (BM * ASTH)      // 5120 halves
#define B_H  (BK * BSTH)      // 2304 halves

// ================= GEMM1: x @ w13 -> SwiGLU -> g_interh =================
#define G1_STH  (A_H + 2 * B_H)            // 9728 halves / stage
#define G1_SMEM (2 * G1_STH * 2)           // 38912 bytes

__global__ __launch_bounds__(256, 2) void gemm1_kernel(const float* __restrict__ w13) {
    extern __shared__ uint16_t sm[];
    __shared__ int s_tok[BM];

    const int e = blockIdx.z;
    const int seg = g_offsets[e];
    const int rows = g_offsets[e + 1] - seg;
    const int m0 = blockIdx.y * BM;
    if (m0 >= rows) return;
    const int n0 = blockIdx.x * 64;
    const int tid = threadIdx.x;
    const int warp = tid >> 5, lane = tid & 31;
    const int wm = (warp >> 1) * 32, wn = (warp & 1) * 32;
    const int qid = lane >> 2, tq = lane & 3;

    if (tid < BM) {
        int gr = m0 + tid;
        s_tok[tid] = (gr < rows) ? g_row_token[seg + gr] : -1;
    }
    __syncthreads();

    // A cp.async roles: 2x 16B per thread (row = tid>>1, halves seg (tid&1)*2 + j)
    const int a_row = tid >> 1;
    const int a_seg = (tid & 1) * 2;
    const int tok_a = s_tok[a_row];
    const uint16_t* a_src0 = (tok_a >= 0) ? (g_xh + (size_t)tok_a * HDIM) : g_xh;
    const uint32_t a_sz = (tok_a >= 0) ? 16u : 0u;

    // B loader roles: warps 0-3 -> gate, warps 4-7 -> up; 4 float4 per thread
    const int mat = tid >> 7;              // 0: gate, 1: up
    const int hh  = tid & 127;
    const int bk0 = hh >> 4;               // base k row (0..7), +8j
    const int bnq = hh & 15;               // float4 index within 64 cols
    const float* wmatb = w13 + (size_t)e * HDIM * (2 * IDIM) + (mat ? IDIM : 0) + n0 + bnq * 4;

    // ldmatrix per-thread address components
    const int lm_t = lane >> 3, lm_r = lane & 7;
    const int lm_krow = (lm_t & 1) * 8 + lm_r;
    const int lm_ncol = wn + (lm_t >> 1) * 8;

    auto cp_a = [&](int c, int s) {
        uint16_t* As = sm + s * G1_STH;
        const int k0 = c * BK;
#pragma unroll
        for (int j = 0; j < 2; j++) {
            int sg = a_seg + j;
            CP_ASYNC16Z(smem_u32(&As[a_row * ASTH + sg * 8]), a_src0 + k0 + sg * 8, a_sz);
        }
    };

    float4 stg[4];
    auto ldg_b = [&](int c) {
        const int k0 = c * BK;
#pragma unroll
        for (int j = 0; j < 4; j++)
            stg[j] = *(const float4*)(wmatb + (size_t)(k0 + bk0 + 8 * j) * (2 * IDIM));
    };
    auto sts_b = [&](int s) {
        uint16_t* Bb = sm + s * G1_STH + A_H + mat * B_H;
#pragma unroll
        for (int j = 0; j < 4; j++) {
            __half2 lo = __floats2half2_rn(stg[j].x, stg[j].y);
            __half2 hi = __floats2half2_rn(stg[j].z, stg[j].w);
            uint2 v;
            v.x = *(uint32_t*)&lo;
            v.y = *(uint32_t*)&hi;
            *(uint2*)&Bb[(bk0 + 8 * j) * BSTH + bnq * 4] = v;
        }
    };

    float accg[2][4][4] = {};
    float accu[2][4][4] = {};

    ldg_b(0); cp_a(0, 0); CP_COMMIT(); sts_b(0); CP_WAIT0();
    __syncthreads();

    const int NC = HDIM / BK;   // 32
    for (int c = 0; c < NC; c++) {
        const int s = c & 1;
        if (c + 1 < NC) { ldg_b(c + 1); cp_a(c + 1, 1 - s); CP_COMMIT(); }

        const uint16_t* As = sm + s * G1_STH;
        const uint16_t* Bg = As + A_H;
        const uint16_t* Bu = Bg + B_H;
        const uint32_t* As32 = (const uint32_t*)As;

#pragma unroll
        for (int ks = 0; ks < BK; ks += 16) {
            uint32_t af[2][4];
#pragma unroll
            for (int mt = 0; mt < 2; mt++) {
                int r = wm + mt * 16 + qid;
                int kw = ks / 2 + tq;
                af[mt][0] = As32[r * 20 + kw];
                af[mt][1] = As32[(r + 8) * 20 + kw];
                af[mt][2] = As32[r * 20 + kw + 4];
                af[mt][3] = As32[(r + 8) * 20 + kw + 4];
            }
#pragma unroll
            for (int pair = 0; pair < 2; pair++) {
                uint32_t bg[4], bu[4];
                uint32_t ag = smem_u32(&Bg[(ks + lm_krow) * BSTH + lm_ncol + pair * 16]);
                uint32_t au = smem_u32(&Bu[(ks + lm_krow) * BSTH + lm_ncol + pair * 16]);
                ldsm_x4_trans(bg, ag);
                ldsm_x4_trans(bu, au);
#pragma unroll
                for (int sub = 0; sub < 2; sub++) {
                    int nt = pair * 2 + sub;
#pragma unroll
                    for (int mt = 0; mt < 2; mt++) {
                        mma_f16(accg[mt][nt], af[mt], bg[sub * 2], bg[sub * 2 + 1]);
                        mma_f16(accu[mt][nt], af[mt], bu[sub * 2], bu[sub * 2 + 1]);
                    }
                }
            }
        }
        if (c + 1 < NC) { sts_b(1 - s); CP_WAIT0(); }
        __syncthreads();
    }

    // epilogue: SwiGLU -> g_interh (packed half2 stores)
#pragma unroll
    for (int mt = 0; mt < 2; mt++) {
#pragma unroll
        for (int nt = 0; nt < 4; nt++) {
            int rbase = wm + mt * 16 + qid;
            int cbase = n0 + wn + nt * 8 + tq * 2;
#pragma unroll
            for (int p = 0; p < 2; p++) {
                int gr = m0 + rbase + p * 8;
                if (gr < rows) {
                    float g0 = accg[mt][nt][p * 2 + 0], u0 = accu[mt][nt][p * 2 + 0];
                    float g1 = accg[mt][nt][p * 2 + 1], u1 = accu[mt][nt][p * 2 + 1];
                    float v0 = g0 / (1.0f + expf(-g0)) * u0;
                    float v1 = g1 / (1.0f + expf(-g1)) * u1;
                    __half2 h = __floats2half2_rn(v0, v1);
                    *(uint32_t*)&g_interh[(size_t)(seg + gr) * IDIM + cbase] = *(uint32_t*)&h;
                }
            }
        }
    }
}

// ================= GEMM2: g_interh @ w2 -> g_out_slot =================
#define G2_STH  (A_H + B_H)                // 7424 halves / stage
#define G2_SMEM (2 * G2_STH * 2)           // 29696 bytes

__global__ __launch_bounds__(256, 2) void gemm2_kernel(const float* __restrict__ w2) {
    extern __shared__ uint16_t sm[];

    const int e = blockIdx.z;
    const int seg = g_offsets[e];
    const int rows = g_offsets[e + 1] - seg;
    const int m0 = blockIdx.y * BM;
    if (m0 >= rows) return;
    const int n0 = blockIdx.x * 64;
    const int tid = threadIdx.x;
    const int warp = tid >> 5, lane = tid & 31;
    const int wm = (warp >> 1) * 32, wn = (warp & 1) * 32;
    const int qid = lane >> 2, tq = lane & 3;

    const int a_row = tid >> 1;
    const int a_seg = (tid & 1) * 2;
    const int gra = m0 + a_row;
    const bool avalid = (gra < rows);
    const uint16_t* a_src0 = avalid ? (g_interh + (size_t)(seg + gra) * IDIM) : g_interh;
    const uint32_t a_sz = avalid ? 16u : 0u;

    const int bk0 = tid >> 4;              // 0..15, +16j
    const int bnq = tid & 15;
    const float* wb = w2 + (size_t)e * IDIM * HDIM + n0 + bnq * 4;

    const int lm_t = lane >> 3, lm_r = lane & 7;
    const int lm_krow = (lm_t & 1) * 8 + lm_r;
    const int lm_ncol = wn + (lm_t >> 1) * 8;

    auto cp_a = [&](int c, int s) {
        uint16_t* As = sm + s * G2_STH;
        const int k0 = c * BK;
#pragma unroll
        for (int j = 0; j < 2; j++) {
            int sg = a_seg + j;
            CP_ASYNC16Z(smem_u32(&As[a_row * ASTH + sg * 8]), a_src0 + k0 + sg * 8, a_sz);
        }
    };

    float4 stg[2];
    auto ldg_b = [&](int c) {
        const int k0 = c * BK;
#pragma unroll
        for (int j = 0; j < 2; j++)
            stg[j] = *(const float4*)(wb + (size_t)(k0 + bk0 + 16 * j) * HDIM);
    };
    auto sts_b = [&](int s) {
        uint16_t* Bb = sm + s * G2_STH + A_H;
#pragma unroll
        for (int j = 0; j < 2; j++) {
            __half2 lo = __floats2half2_rn(stg[j].x, stg[j].y);
            __half2 hi = __floats2half2_rn(stg[j].z, stg[j].w);
            uint2 v;
            v.x = *(uint32_t*)&lo;
            v.y = *(uint32_t*)&hi;
            *(uint2*)&Bb[(bk0 + 16 * j) * BSTH + bnq * 4] = v;
        }
    };

    float acc[2][4][4] = {};

    ldg_b(0); cp_a(0, 0); CP_COMMIT(); sts_b(0); CP_WAIT0();
    __syncthreads();

    const int NC = IDIM / BK;   // 32
    for (int c = 0; c < NC; c++) {
        const int s = c & 1;
        if (c + 1 < NC) { ldg_b(c + 1); cp_a(c + 1, 1 - s); CP_COMMIT(); }

        const uint16_t* As = sm + s * G2_STH;
        const uint16_t* Bs = As + A_H;
        const uint32_t* As32 = (const uint32_t*)As;

#pragma unroll
        for (int ks = 0; ks < BK; ks += 16) {
            uint32_t af[2][4];
#pragma unroll
            for (int mt = 0; mt < 2; mt++) {
                int r = wm + mt * 16 + qid;
                int kw = ks / 2 + tq;
                af[mt][0] = As32[r * 20 + kw];
                af[mt][1] = As32[(r + 8) * 20 + kw];
                af[mt][2] = As32[r * 20 + kw + 4];
                af[mt][3] = As32[(r + 8) * 20 + kw + 4];
            }
#pragma unroll
            for (int pair = 0; pair < 2; pair++) {
                uint32_t bb[4];
                uint32_t ab = smem_u32(&Bs[(ks + lm_krow) * BSTH + lm_ncol + pair * 16]);
                ldsm_x4_trans(bb, ab);
#pragma unroll
                for (int sub = 0; sub < 2; sub++) {
                    int nt = pair * 2 + sub;
#pragma unroll
                    for (int mt = 0; mt < 2; mt++) {
                        mma_f16(acc[mt][nt], af[mt], bb[sub * 2], bb[sub * 2 + 1]);
                    }
                }
            }
        }
        if (c + 1 < NC) { sts_b(1 - s); CP_WAIT0(); }
        __syncthreads();
    }

#pragma unroll
    for (int mt = 0; mt < 2; mt++) {
#pragma unroll
        for (int nt = 0; nt < 4; nt++) {
            int rbase = wm + mt * 16 + qid;
            int cbase = n0 + wn + nt * 8 + tq * 2;
#pragma unroll
            for (int p = 0; p < 2; p++) {
                int gr = m0 + rbase + p * 8;
                if (gr < rows) {
                    float2 v = make_float2(acc[mt][nt][p * 2 + 0], acc[mt][nt][p * 2 + 1]);
                    *(float2*)&g_out_slot[(size_t)(seg + gr) * HDIM + cbase] = v;
                }
            }
        }
    }
}

// ---------------- combine: out[t] = w0*slot[s0] + w1*slot[s1] ----------------
__global__ __launch_bounds__(256) void combine_kernel(float* __restrict__ out) {
    int idx = blockIdx.x * blockDim.x + threadIdx.x;
    int t = idx / (HDIM / 4);
    int c4 = (idx % (HDIM / 4)) * 4;
    if (t >= T_TOK) return;
    int s0 = g_tok_slot[2 * t];
    int s1 = g_tok_slot[2 * t + 1];
    float w0 = g_tok_w[2 * t];
    float w1 = g_tok_w[2 * t + 1];
    float4 a = *(const float4*)&g_out_slot[(size_t)s0 * HDIM + c4];
    float4 b = *(const float4*)&g_out_slot[(size_t)s1 * HDIM + c4];
    float4 r;
    r.x = w0 * a.x + w1 * b.x;
    r.y = w0 * a.y + w1 * b.y;
    r.z = w0 * a.z + w1 * b.z;
    r.w = w0 * a.w + w1 * b.w;
    *(float4*)&out[(size_t)t * HDIM + c4] = r;
}

// ---------------- launch ----------------
extern "C" void kernel_launch(void* const* d_in, const int* in_sizes, int n_in,
                              void* d_out, int out_size) {
    const float* x      = (const float*)d_in[0];
    const float* logits = (const float*)d_in[1];
    const float* w13    = (const float*)d_in[2];
    const float* w2     = (const float*)d_in[3];
    float* out = (float*)d_out;

    route_kernel<<<1, 1024>>>(logits);
    cvt_x_kernel<<<T_TOK * HDIM / 4 / 256, 256>>>(x);

    gemm1_kernel<<<dim3(IDIM / 64, 16, NEXP), 256, G1_SMEM>>>(w13);
    gemm2_kernel<<<dim3(HDIM / 64, 16, NEXP), 256, G2_SMEM>>>(w2);

    combine_kernel<<<T_TOK * HDIM / 4 / 256, 256>>>(out);
}